// round 4
// baseline (speedup 1.0000x reference)
#include <cuda_runtime.h>

// WeightedAggregator: out[b, :] = sum_k (w[b,k] / sum_j w[b,j]) * features[idx[b,k], :]
// B = 50000, K = 16, D = 128 (fp32). One warp per output row; one float4 per lane.
// NOTE: neigh_idx is int32 — JAX demotes jnp.int64 to int32 without x64 mode.

#define K_NEIGH 16
#define FEAT_D 128   // floats per row; 32 float4 per row -> 1 float4 per lane

__global__ __launch_bounds__(256)
void weighted_agg_kernel(const float* __restrict__ features,
                         const float* __restrict__ neigh_w,
                         const int* __restrict__ neigh_idx,
                         float* __restrict__ out,
                         int B)
{
    const int gtid = blockIdx.x * blockDim.x + threadIdx.x;
    const int row  = gtid >> 5;          // warp id = output row
    const int lane = threadIdx.x & 31;
    if (row >= B) return;

    // Lanes 0..15 hold this row's weight + index; others hold 0.
    float w  = 0.0f;
    int   ix = 0;
    if (lane < K_NEIGH) {
        w  = neigh_w  [row * K_NEIGH + lane];
        ix = neigh_idx[row * K_NEIGH + lane];
    }

    // Warp-wide sum of weights (lanes >= 16 contribute 0).
    float s = w;
    #pragma unroll
    for (int off = 16; off > 0; off >>= 1)
        s += __shfl_xor_sync(0xffffffffu, s, off);
    const float inv = 1.0f / s;   // same value in every lane

    const float4* __restrict__ feat4 = (const float4*)features;

    // Phase 1: batch all 16 gather loads (front-batched -> MLP=16 per thread).
    float4 f[K_NEIGH];
    #pragma unroll
    for (int k = 0; k < K_NEIGH; k++) {
        const int ik = __shfl_sync(0xffffffffu, ix, k);
        f[k] = __ldg(feat4 + (long long)ik * (FEAT_D / 4) + lane);
    }

    // Phase 2: weighted accumulation. Two independent chains to shorten the
    // FFMA dependency chain (4-cyc RAW latency).
    float4 a0 = make_float4(0.f, 0.f, 0.f, 0.f);
    float4 a1 = make_float4(0.f, 0.f, 0.f, 0.f);
    #pragma unroll
    for (int k = 0; k < K_NEIGH; k += 2) {
        const float w0 = __shfl_sync(0xffffffffu, w, k);
        const float w1 = __shfl_sync(0xffffffffu, w, k + 1);
        a0.x += w0 * f[k].x;     a1.x += w1 * f[k + 1].x;
        a0.y += w0 * f[k].y;     a1.y += w1 * f[k + 1].y;
        a0.z += w0 * f[k].z;     a1.z += w1 * f[k + 1].z;
        a0.w += w0 * f[k].w;     a1.w += w1 * f[k + 1].w;
    }

    float4 r;
    r.x = (a0.x + a1.x) * inv;
    r.y = (a0.y + a1.y) * inv;
    r.z = (a0.z + a1.z) * inv;
    r.w = (a0.w + a1.w) * inv;

    ((float4*)out)[(long long)row * (FEAT_D / 4) + lane] = r;
}

extern "C" void kernel_launch(void* const* d_in, const int* in_sizes, int n_in,
                              void* d_out, int out_size)
{
    const float* features  = (const float*)d_in[0];   // [N_NODES, 128] fp32
    const float* neigh_w   = (const float*)d_in[1];   // [B, 16] fp32
    const int*   neigh_idx = (const int*)d_in[2];     // [B, 16] int32 (JAX demotes int64)
    float*       out       = (float*)d_out;           // [B, 128] fp32

    const int B = in_sizes[1] / K_NEIGH;   // 50000

    const int threads = 256;               // 8 warps/block -> 8 rows/block
    const int rows_per_block = threads / 32;
    const int blocks = (B + rows_per_block - 1) / rows_per_block;

    weighted_agg_kernel<<<blocks, threads>>>(features, neigh_w, neigh_idx, out, B);
}